// round 5
// baseline (speedup 1.0000x reference)
#include <cuda_runtime.h>

// SpatialTransformer3D: B=4, vol 128^3, C=2, resampled 128^3.
// Tile 32(i1) x 32(i2); lanes along i1 (coalesced gathers), smem transpose
// (split float planes, conflict-free) for coalesced stores along i2.
// Pairs of i2-steps: step B reuses step A's high-z corners when the exact
// integer corner indices match (checked per-lane); B's low-z gathers are
// predicated off on reuse -> no L1 wavefronts for them.

#define R3_ (128*128*128)

__device__ __forceinline__ int clampi(int v, int lo, int hi) {
    return v < lo ? lo : (v > hi ? hi : v);
}

struct Corner {
    int x0, x1;
    int r00, r01, r10, r11;   // row offsets (float2 units): z*16384 + y*128
    float wx0, wx1, wy0, wy1, wz0, wz1;
};

__device__ __forceinline__ Corner make_corner(float x, float y, float z) {
    Corner c;
    int xi = (int)x, yi = (int)y, zi = (int)z;   // trunc toward zero (matches astype)
    c.x0 = clampi(xi,     0, 127);
    c.x1 = clampi(xi + 1, 0, 127);
    int y0 = clampi(yi,     0, 127);
    int y1 = clampi(yi + 1, 0, 127);
    int z0 = clampi(zi,     0, 127);
    int z1 = clampi(zi + 1, 0, 127);
    c.wx0 = (float)c.x1 - x;  c.wx1 = x - (float)c.x0;
    c.wy0 = (float)y1   - y;  c.wy1 = y - (float)y0;
    c.wz0 = (float)z1   - z;  c.wz1 = z - (float)z0;
    int iz0 = z0 << 14, iz1 = z1 << 14;
    int iy0 = y0 << 7,  iy1 = y1 << 7;
    c.r00 = iz0 + iy0;  c.r01 = iz0 + iy1;
    c.r10 = iz1 + iy0;  c.r11 = iz1 + iy1;
    return c;
}

// Predicated vector load: when cond==0 the LDG is predicated off (no L1
// wavefronts, result undefined -> caller selects the reuse value instead).
__device__ __forceinline__ float2 ldg_cond(const float2* p, int cond) {
    float2 v;
    asm volatile(
        "{\n\t"
        ".reg .pred lp;\n\t"
        "setp.ne.s32 lp, %3, 0;\n\t"
        "@lp ld.global.nc.v2.f32 {%0, %1}, [%2];\n\t"
        "}"
        : "=f"(v.x), "=f"(v.y)
        : "l"(p), "r"(cond));
    return v;
}

__device__ __forceinline__ float2 lerp8(const Corner& c,
    float2 c000, float2 c001, float2 c010, float2 c011,
    float2 c100, float2 c101, float2 c110, float2 c111)
{
    float wxy00 = c.wx0 * c.wy0;
    float wxy01 = c.wx0 * c.wy1;
    float wxy10 = c.wx1 * c.wy0;
    float wxy11 = c.wx1 * c.wy1;
    float w000 = wxy00 * c.wz0, w100 = wxy00 * c.wz1;
    float w010 = wxy01 * c.wz0, w110 = wxy01 * c.wz1;
    float w001 = wxy10 * c.wz0, w101 = wxy10 * c.wz1;
    float w011 = wxy11 * c.wz0, w111 = wxy11 * c.wz1;

    float2 acc;
    acc.x = w000 * c000.x;                 acc.y = w000 * c000.y;
    acc.x = fmaf(w100, c100.x, acc.x);     acc.y = fmaf(w100, c100.y, acc.y);
    acc.x = fmaf(w010, c010.x, acc.x);     acc.y = fmaf(w010, c010.y, acc.y);
    acc.x = fmaf(w110, c110.x, acc.x);     acc.y = fmaf(w110, c110.y, acc.y);
    acc.x = fmaf(w001, c001.x, acc.x);     acc.y = fmaf(w001, c001.y, acc.y);
    acc.x = fmaf(w101, c101.x, acc.x);     acc.y = fmaf(w101, c101.y, acc.y);
    acc.x = fmaf(w011, c011.x, acc.x);     acc.y = fmaf(w011, c011.y, acc.y);
    acc.x = fmaf(w111, c111.x, acc.x);     acc.y = fmaf(w111, c111.y, acc.y);
    return acc;
}

__global__ __launch_bounds__(256, 4)
void st3d_kernel(const float* __restrict__ images,
                 const float* __restrict__ params,
                 float2* __restrict__ out)
{
    __shared__ float tx[32][33];   // acc.x plane (conflict-free transpose)
    __shared__ float ty[32][33];   // acc.y plane

    int t    = threadIdx.x;
    int lane = t & 31;
    int warp = t >> 5;

    int blk = blockIdx.x;
    int i2t = (blk & 3) << 5;
    int i1t = ((blk >> 2) & 3) << 5;
    int i0  = (blk >> 4) & 127;
    int b   = blk >> 11;

    const float* m = params + b * 12;
    float m00 = __ldg(m+0),  m01 = __ldg(m+1),  m02 = __ldg(m+2),  m03 = __ldg(m+3);
    float m10 = __ldg(m+4),  m11 = __ldg(m+5),  m12 = __ldg(m+6),  m13 = __ldg(m+7);
    float m20 = __ldg(m+8),  m21 = __ldg(m+9),  m22 = __ldg(m+10), m23 = __ldg(m+11);

    const float step = 2.0f / 127.0f;
    int i1 = i1t + lane;
    float xn = fmaf((float)i1, step, -1.0f);
    float yn = fmaf((float)i0, step, -1.0f);

    // x(fi2) = dxz*fi2 + cx   with fi2 = i2 index as float (exact)
    // where x = ( m0.·(xn,yn,zn,1) + 1 ) * 64,  zn = fi2*step - 1
    float gx = fmaf(m00, xn, fmaf(m01, yn, m03));
    float gy = fmaf(m10, xn, fmaf(m11, yn, m13));
    float gz = fmaf(m20, xn, fmaf(m21, yn, m23));
    float dxz = 64.0f * step * m02;
    float dyz = 64.0f * step * m12;
    float dzz = 64.0f * step * m22;
    float cx = (gx - m02 + 1.0f) * 64.0f;
    float cy = (gy - m12 + 1.0f) * 64.0f;
    float cz = (gz - m22 + 1.0f) * 64.0f;

    const float2* __restrict__ vol = (const float2*)images + (size_t)b * R3_;

    int i2base = i2t + (warp << 2);
    float fbase = (float)i2base;

    #pragma unroll
    for (int jj = 0; jj < 2; jj++) {
        float fA = fbase + (float)(jj * 2);
        float fB = fA + 1.0f;

        float xA = fmaf(dxz, fA, cx);
        float yA = fmaf(dyz, fA, cy);
        float zA = fmaf(dzz, fA, cz);
        float xB = fmaf(dxz, fB, cx);
        float yB = fmaf(dyz, fB, cy);
        float zB = fmaf(dzz, fB, cz);

        Corner A = make_corner(xA, yA, zA);
        Corner B = make_corner(xB, yB, zB);

        // A: full 8 gathers
        float2 a000 = __ldg(vol + A.r00 + A.x0);
        float2 a100 = __ldg(vol + A.r10 + A.x0);
        float2 a010 = __ldg(vol + A.r01 + A.x0);
        float2 a110 = __ldg(vol + A.r11 + A.x0);
        float2 a001 = __ldg(vol + A.r00 + A.x1);
        float2 a101 = __ldg(vol + A.r10 + A.x1);
        float2 a011 = __ldg(vol + A.r01 + A.x1);
        float2 a111 = __ldg(vol + A.r11 + A.x1);

        // B high-z: always loaded
        float2 b100 = __ldg(vol + B.r10 + B.x0);
        float2 b110 = __ldg(vol + B.r11 + B.x0);
        float2 b101 = __ldg(vol + B.r10 + B.x1);
        float2 b111 = __ldg(vol + B.r11 + B.x1);

        // B low-z: reuse A high-z when exact corner indices match
        int ru = (A.r10 ^ B.r00) | (A.r11 ^ B.r01) |
                 (A.x0  ^ B.x0)  | (A.x1  ^ B.x1);
        float2 t000 = ldg_cond(vol + B.r00 + B.x0, ru);
        float2 t010 = ldg_cond(vol + B.r01 + B.x0, ru);
        float2 t001 = ldg_cond(vol + B.r00 + B.x1, ru);
        float2 t011 = ldg_cond(vol + B.r01 + B.x1, ru);

        int jA = (warp << 2) + jj * 2;

        float2 accA = lerp8(A, a000, a001, a010, a011, a100, a101, a110, a111);
        tx[jA][lane] = accA.x;
        ty[jA][lane] = accA.y;

        bool re = (ru == 0);
        float2 b000, b010, b001, b011;
        b000.x = re ? a100.x : t000.x;   b000.y = re ? a100.y : t000.y;
        b010.x = re ? a110.x : t010.x;   b010.y = re ? a110.y : t010.y;
        b001.x = re ? a101.x : t001.x;   b001.y = re ? a101.y : t001.y;
        b011.x = re ? a111.x : t011.x;   b011.y = re ? a111.y : t011.y;

        float2 accB = lerp8(B, b000, b001, b010, b011, b100, b101, b110, b111);
        tx[jA + 1][lane] = accB.x;
        ty[jA + 1][lane] = accB.y;
    }

    __syncthreads();

    size_t out_base = ((size_t)b << 21) + ((size_t)i0 << 14);
    #pragma unroll
    for (int j = 0; j < 4; j++) {
        int i1l = warp + (j << 3);
        float2 v;
        v.x = tx[lane][i1l];
        v.y = ty[lane][i1l];
        out[out_base + (size_t)(i1t + i1l) * 128 + (i2t + lane)] = v;
    }
}

extern "C" void kernel_launch(void* const* d_in, const int* in_sizes, int n_in,
                              void* d_out, int out_size)
{
    const float* images = (const float*)d_in[0];
    const float* params = (const float*)d_in[1];
    float2* out = (float2*)d_out;

    st3d_kernel<<<8192, 256>>>(images, params, out);
}

// round 6
// speedup vs baseline: 1.0531x; 1.0531x over previous
#include <cuda_runtime.h>

// SpatialTransformer3D: B=4, vol 128^3, C=2, resampled 128^3.
// Tile 32(i1) x 32(i2); lanes along i1 (coalesced gathers), conflict-free
// split-plane smem transpose for coalesced stores along i2.
// Each warp walks 4 consecutive i2 steps as a CHAIN: step j+1's low-z corners
// reuse step j's high-z registers; a single predicated 4-load asm block
// overwrites them only when the exact integer corner indices differ.

#define R3_ (128*128*128)

__device__ __forceinline__ int clampi(int v, int lo, int hi) {
    return v < lo ? lo : (v > hi ? hi : v);
}

struct Crn {
    int x0, x1;
    int r00, r01, r10, r11;   // (z<<14)+(y<<7) combos, float2 units
    float x, y, z;            // raw coords (weights derived lazily)
    int y0, y1, z0, z1;
};

__device__ __forceinline__ Crn make_crn(float x, float y, float z) {
    Crn c;
    int xi = (int)x, yi = (int)y, zi = (int)z;   // trunc toward zero (astype)
    c.x0 = clampi(xi,     0, 127);
    c.x1 = clampi(xi + 1, 0, 127);
    c.y0 = clampi(yi,     0, 127);
    c.y1 = clampi(yi + 1, 0, 127);
    c.z0 = clampi(zi,     0, 127);
    c.z1 = clampi(zi + 1, 0, 127);
    int iz0 = c.z0 << 14, iz1 = c.z1 << 14;
    int iy0 = c.y0 << 7,  iy1 = c.y1 << 7;
    c.r00 = iz0 + iy0;  c.r01 = iz0 + iy1;
    c.r10 = iz1 + iy0;  c.r11 = iz1 + iy1;
    c.x = x; c.y = y; c.z = z;
    return c;
}

// Weighted sum; corner naming: bit2=z, bit1=y, bit0=x (e.g. v100 = z1,y0,x0)
__device__ __forceinline__ float2 lerp8(const Crn& c,
    float2 v000, float2 v001, float2 v010, float2 v011,
    float2 v100, float2 v101, float2 v110, float2 v111)
{
    float wx0 = (float)c.x1 - c.x, wx1 = c.x - (float)c.x0;
    float wy0 = (float)c.y1 - c.y, wy1 = c.y - (float)c.y0;
    float wz0 = (float)c.z1 - c.z, wz1 = c.z - (float)c.z0;

    float wxy00 = wx0 * wy0;
    float wxy01 = wx0 * wy1;
    float wxy10 = wx1 * wy0;
    float wxy11 = wx1 * wy1;
    float w000 = wxy00 * wz0, w100 = wxy00 * wz1;
    float w010 = wxy01 * wz0, w110 = wxy01 * wz1;
    float w001 = wxy10 * wz0, w101 = wxy10 * wz1;
    float w011 = wxy11 * wz0, w111 = wxy11 * wz1;

    float2 acc;
    acc.x = w000 * v000.x;                 acc.y = w000 * v000.y;
    acc.x = fmaf(w100, v100.x, acc.x);     acc.y = fmaf(w100, v100.y, acc.y);
    acc.x = fmaf(w010, v010.x, acc.x);     acc.y = fmaf(w010, v010.y, acc.y);
    acc.x = fmaf(w110, v110.x, acc.x);     acc.y = fmaf(w110, v110.y, acc.y);
    acc.x = fmaf(w001, v001.x, acc.x);     acc.y = fmaf(w001, v001.y, acc.y);
    acc.x = fmaf(w101, v101.x, acc.x);     acc.y = fmaf(w101, v101.y, acc.y);
    acc.x = fmaf(w011, v011.x, acc.x);     acc.y = fmaf(w011, v011.y, acc.y);
    acc.x = fmaf(w111, v111.x, acc.x);     acc.y = fmaf(w111, v111.y, acc.y);
    return acc;
}

__global__ __launch_bounds__(256, 4)
void st3d_kernel(const float* __restrict__ images,
                 const float* __restrict__ params,
                 float2* __restrict__ out)
{
    __shared__ float tx[32][33];
    __shared__ float ty[32][33];

    int t    = threadIdx.x;
    int lane = t & 31;
    int warp = t >> 5;

    int blk = blockIdx.x;
    int i2t = (blk & 3) << 5;
    int i1t = ((blk >> 2) & 3) << 5;
    int i0  = (blk >> 4) & 127;
    int b   = blk >> 11;

    const float* m = params + b * 12;
    float m00 = __ldg(m+0),  m01 = __ldg(m+1),  m02 = __ldg(m+2),  m03 = __ldg(m+3);
    float m10 = __ldg(m+4),  m11 = __ldg(m+5),  m12 = __ldg(m+6),  m13 = __ldg(m+7);
    float m20 = __ldg(m+8),  m21 = __ldg(m+9),  m22 = __ldg(m+10), m23 = __ldg(m+11);

    const float step = 2.0f / 127.0f;
    int i1 = i1t + lane;
    float xn = fmaf((float)i1, step, -1.0f);
    float yn = fmaf((float)i0, step, -1.0f);

    // coord(fi2) = d.z * fi2 + c.   (exact same fp result as the reference
    // composition because each is a single fmaf chain on identical inputs)
    float gx = fmaf(m00, xn, fmaf(m01, yn, m03));
    float gy = fmaf(m10, xn, fmaf(m11, yn, m13));
    float gz = fmaf(m20, xn, fmaf(m21, yn, m23));
    float dxz = 64.0f * step * m02;
    float dyz = 64.0f * step * m12;
    float dzz = 64.0f * step * m22;
    float cx = (gx - m02 + 1.0f) * 64.0f;
    float cy = (gy - m12 + 1.0f) * 64.0f;
    float cz = (gz - m22 + 1.0f) * 64.0f;

    const float2* __restrict__ vol = (const float2*)images + (size_t)b * R3_;

    int i2base = i2t + (warp << 2);
    float fb = (float)i2base;

    // prologue: step 0 corners + full 8 gathers
    Crn c = make_crn(fmaf(dxz, fb, cx), fmaf(dyz, fb, cy), fmaf(dzz, fb, cz));

    float2 v000 = __ldg(vol + c.r00 + c.x0);
    float2 v010 = __ldg(vol + c.r01 + c.x0);
    float2 v001 = __ldg(vol + c.r00 + c.x1);
    float2 v011 = __ldg(vol + c.r01 + c.x1);
    float2 v100 = __ldg(vol + c.r10 + c.x0);
    float2 v110 = __ldg(vol + c.r11 + c.x0);
    float2 v101 = __ldg(vol + c.r10 + c.x1);
    float2 v111 = __ldg(vol + c.r11 + c.x1);

    #pragma unroll
    for (int j = 0; j < 4; j++) {
        int row = (warp << 2) + j;

        if (j < 3) {
            float fn = fb + (float)(j + 1);
            Crn n = make_crn(fmaf(dxz, fn, cx), fmaf(dyz, fn, cy), fmaf(dzz, fn, cz));

            // next step's high-z corners: always loaded (issued early)
            float2 h100 = __ldg(vol + n.r10 + n.x0);
            float2 h110 = __ldg(vol + n.r11 + n.x0);
            float2 h101 = __ldg(vol + n.r10 + n.x1);
            float2 h111 = __ldg(vol + n.r11 + n.x1);

            // addresses for the (rarely-taken) low-z reload
            const float2* p000 = vol + n.r00 + n.x0;
            const float2* p010 = vol + n.r01 + n.x0;
            const float2* p001 = vol + n.r00 + n.x1;
            const float2* p011 = vol + n.r01 + n.x1;

            // consume current step
            float2 acc = lerp8(c, v000, v001, v010, v011, v100, v101, v110, v111);
            tx[row][lane] = acc.x;
            ty[row][lane] = acc.y;

            // reuse check: n's low-z corner set vs c's high-z corner set
            int ru = (n.r00 ^ c.r10) | (n.r01 ^ c.r11) |
                     (n.x0  ^ c.x0)  | (n.x1  ^ c.x1);

            // shift high -> low (register renames after unroll)
            v000 = v100; v010 = v110; v001 = v101; v011 = v111;

            // overwrite low-z only when corner indices differ (ru != 0);
            // predicated-off lanes generate no L1 wavefronts.
            asm volatile(
                "{\n\t"
                ".reg .pred p;\n\t"
                "setp.ne.s32 p, %8, 0;\n\t"
                "@p ld.global.nc.v2.f32 {%0, %1}, [%9];\n\t"
                "@p ld.global.nc.v2.f32 {%2, %3}, [%10];\n\t"
                "@p ld.global.nc.v2.f32 {%4, %5}, [%11];\n\t"
                "@p ld.global.nc.v2.f32 {%6, %7}, [%12];\n\t"
                "}"
                : "+f"(v000.x), "+f"(v000.y), "+f"(v010.x), "+f"(v010.y),
                  "+f"(v001.x), "+f"(v001.y), "+f"(v011.x), "+f"(v011.y)
                : "r"(ru), "l"(p000), "l"(p010), "l"(p001), "l"(p011));

            v100 = h100; v110 = h110; v101 = h101; v111 = h111;
            c = n;
        } else {
            float2 acc = lerp8(c, v000, v001, v010, v011, v100, v101, v110, v111);
            tx[row][lane] = acc.x;
            ty[row][lane] = acc.y;
        }
    }

    __syncthreads();

    size_t out_base = ((size_t)b << 21) + ((size_t)i0 << 14);
    #pragma unroll
    for (int j = 0; j < 4; j++) {
        int i1l = warp + (j << 3);
        float2 v;
        v.x = tx[lane][i1l];
        v.y = ty[lane][i1l];
        out[out_base + (size_t)(i1t + i1l) * 128 + (i2t + lane)] = v;
    }
}

extern "C" void kernel_launch(void* const* d_in, const int* in_sizes, int n_in,
                              void* d_out, int out_size)
{
    const float* images = (const float*)d_in[0];
    const float* params = (const float*)d_in[1];
    float2* out = (float2*)d_out;

    st3d_kernel<<<8192, 256>>>(images, params, out);
}